// round 7
// baseline (speedup 1.0000x reference)
#include <cuda_runtime.h>
#include <math.h>

#define NN   20000
#define FF   64
#define EE   320000
#define GG   20
#define NGG  1000
#define NELS 10
#define NBB  8
#define RMAXF 5.0f
#define HML  16

// output layout (float32, 20160 elems):
#define OUT_TE      0        // [20]  total_energy
#define OUT_NE      20       // [20000] node_energy
#define OUT_CONTRIB 20020    // [20,3] contributions
#define OUT_POL     20080    // [20,3] pol
#define OUT_TC      20140    // [20]  total_charge
#define OUT_TOTAL   20160

// ---------------- device scratch (no allocation allowed) ----------------
__device__ float  g_sc[NN * FF];     // current node scalars
__device__ float  g_agg[NN * FF];    // per-layer aggregation (s=0 only!)
__device__ float  g_ef[EE * 16];     // compacted DUPLICATED radial feats (v,v)
__device__ int2   g_aidx[EE];        // compacted (snd, rcv)
__device__ float  g_cd[NN];          // charge density
__device__ float4 g_pos4[NN];        // padded positions (1-sector gathers)
__device__ int    g_count;           // active edge count

// ---------------- PTX helpers ----------------
__device__ __forceinline__ unsigned smem_u32(const void* p) {
    return (unsigned)__cvta_generic_to_shared(p);
}
__device__ __forceinline__ void cp16(unsigned d, const void* g) {
    asm volatile("cp.async.ca.shared.global [%0], [%1], 16;" :: "r"(d), "l"(g));
}
__device__ __forceinline__ void cp8(unsigned d, const void* g) {
    asm volatile("cp.async.ca.shared.global [%0], [%1], 8;" :: "r"(d), "l"(g));
}
#define CP_COMMIT()  asm volatile("cp.async.commit_group;" ::: "memory")
#define CP_WAIT0()   asm volatile("cp.async.wait_group 0;" ::: "memory")

__device__ __forceinline__ unsigned long long pack2(float x, float y) {
    unsigned long long r;
    asm("mov.b64 %0, {%1, %2};" : "=l"(r) : "f"(x), "f"(y));
    return r;
}
__device__ __forceinline__ void ffma2(unsigned long long& d,
                                      unsigned long long a, unsigned long long b) {
    asm("fma.rn.f32x2 %0, %1, %2, %3;" : "=l"(d) : "l"(a), "l"(b), "l"(d));
}
__device__ __forceinline__ float2 unpack2(unsigned long long v) {
    float2 r;
    asm("mov.b64 {%0, %1}, %2;" : "=f"(r.x), "=f"(r.y) : "l"(v));
    return r;
}

// mlp dynamic smem layout (bytes)
#define W2D_OFF  0          // float2[64*66]  pre-duplicated W2^T  (33792 B)
#define HP_OFF   33792      // float2[8][4][64] hidden pairs       (16384 B)
#define EFB_OFF  50176      // float4[2][8][8][4] ef double-buffer  (8192 B)
#define IDB_OFF  58368      // int2[2][8][8]                        (1024 B)
#define MLP_SMEM 59392

// ---------------- K0: zero small accumulator regions ----------------
__global__ void k_zero(float* __restrict__ out) {
    int i = threadIdx.x;
    if (i < GG) out[OUT_TE + i] = 0.0f;                         // total_energy
    if (i < 140) out[OUT_CONTRIB + i] = 0.0f;                   // contrib+pol+tc
    if (i == 0) g_count = 0;
}

// ---------------- K1: node init (embed, E0, FQ, pol, pos4; 4 nodes/block) ---
__global__ void __launch_bounds__(256)
k_node_init(const float* __restrict__ attrs,
            const float* __restrict__ pos,
            const int*   __restrict__ batch,
            const float* __restrict__ ae,
            const float* __restrict__ embw,
            const float* __restrict__ fc,
            float* __restrict__ out) {
    int lg = threadIdx.x >> 6;
    int f  = threadIdx.x & 63;
    int n  = blockIdx.x * 4 + lg;
    __shared__ float at[4][NELS];
    __shared__ float fqs[4];
    if (f < NELS) at[lg][f] = attrs[n * NELS + f];
    __syncthreads();
    float s = 0.0f;
#pragma unroll
    for (int k = 0; k < NELS; k++) s = fmaf(at[lg][k], embw[k * FF + f], s);
    g_sc[n * FF + f] = s;
    g_agg[n * FF + f] = 0.0f;
    if (f == 0) {
        float fq = 0.0f, ne0 = 0.0f;
#pragma unroll
        for (int k = 0; k < NELS; k++) { fq = fmaf(at[lg][k], fc[k], fq); ne0 = fmaf(at[lg][k], ae[k], ne0); }
        g_cd[n] = fq;
        out[OUT_NE + n] = ne0;
        atomicAdd(&out[OUT_CONTRIB + batch[n] * 3 + 0], ne0);
        fqs[lg] = fq;
        g_pos4[n] = make_float4(pos[n * 3 + 0], pos[n * 3 + 1], pos[n * 3 + 2], 0.0f);
    }
    __syncthreads();
    if (f < 3)
        atomicAdd(&out[OUT_POL + batch[n] * 3 + f], fqs[lg] * pos[n * 3 + f]);
}

// ---------------- K2: edge geometry + radial basis + flux/pol + compaction ---
__global__ void __launch_bounds__(256)
k_edge_geom(const int*   __restrict__ ei,
            const int*   __restrict__ batch,
            const float* __restrict__ fw,   // flux_w [2,8]
            float* __restrict__ out) {
    int e = blockIdx.x * 256 + threadIdx.x;    // grid sized exactly EE/256
    int lane = threadIdx.x & 31;
    __shared__ float polsm[GG * 3];
    if (threadIdx.x < GG * 3) polsm[threadIdx.x] = 0.0f;
    __syncthreads();

    int snd = ei[e], rcv = ei[EE + e];
    float4 ps = g_pos4[snd], pr = g_pos4[rcv];
    float dx = pr.x - ps.x, dy = pr.y - ps.y, dz = pr.z - ps.z;
    float d2 = fmaf(dx, dx, fmaf(dy, dy, dz * dz)) + 1e-12f;
    float rinv = rsqrtf(d2);
    float r = d2 * rinv;
    bool active = (r < RMAXF);
    float ef[NBB];
    float flux = 0.0f;
    if (active) {
        float x = r * (1.0f / RMAXF);
        float x2 = x * x;
        float x5 = x2 * x2 * x;
        float u = 1.0f + x5 * (-21.0f + x * (35.0f - 15.0f * x));
        float pref = 0.6324555320336759f * u * rinv;    // sqrt(2/5)*u/r
        float s1, c1;
        __sincosf(r * 0.6283185307179586f, &s1, &c1);   // pi/5 * r
        float sn = s1, cn = c1;
#pragma unroll
        for (int i = 0; i < NBB; i++) {
            float v = pref * sn;
            ef[i] = v;
            flux = fmaf(v, fw[i] + fw[NBB + i], flux);
            float sn2 = sn * c1 + cn * s1;
            cn = cn * c1 - sn * s1;
            sn = sn2;
        }
    }

    unsigned mask = __ballot_sync(0xffffffffu, active);
    if (mask) {
        int leader = __ffs(mask) - 1;
        int cnt = __popc(mask);
        int base = 0;
        if (lane == leader) base = atomicAdd(&g_count, cnt);
        base = __shfl_sync(0xffffffffu, base, leader);
        if (active) {
            int slot = base + __popc(mask & ((1u << lane) - 1u));
            float4* ef4 = (float4*)&g_ef[slot * 16];   // duplicated pairs
            ef4[0] = make_float4(ef[0], ef[0], ef[1], ef[1]);
            ef4[1] = make_float4(ef[2], ef[2], ef[3], ef[3]);
            ef4[2] = make_float4(ef[4], ef[4], ef[5], ef[5]);
            ef4[3] = make_float4(ef[6], ef[6], ef[7], ef[7]);
            g_aidx[slot] = make_int2(snd, rcv);
            int g = batch[rcv];
            atomicAdd(&polsm[g * 3 + 0], flux * dx);
            atomicAdd(&polsm[g * 3 + 1], flux * dy);
            atomicAdd(&polsm[g * 3 + 2], flux * dz);
        }
    }
    __syncthreads();
    if (threadIdx.x < GG * 3) {
        float v = polsm[threadIdx.x];
        if (v != 0.0f) atomicAdd(&out[OUT_POL + threadIdx.x], v);
    }
}

// ---------------- K4: per-edge radial MLP + message scatter (s=0 only) -------
// Warp-local, 8 edges/trip/warp, 2 features/lane. All FFMA2 operands come
// pre-duplicated from smem (zero pack instructions); cp.async double-buffer.
__global__ void __launch_bounds__(256)
k_edge_mlp(const float* __restrict__ W1,   // [8,64]
           const float* __restrict__ B1,   // [64]
           const float* __restrict__ W2) { // [64,64]
    extern __shared__ char smx[];
    float2* w2d = (float2*)(smx + W2D_OFF);   // [f][j] stride 66, (w,w) pairs
    float2* hp  = (float2*)(smx + HP_OFF);    // [(warp*4+ep)*64 + j]
    float4* efb = (float4*)(smx + EFB_OFF);   // [((st*8+warp)*8+e)*4]
    int2*   idb = (int2*)(smx + IDB_OFF);     // [(st*8+warp)*8+e]
    int tid = threadIdx.x;
    int warp = tid >> 5;
    int lane = tid & 31;
    int f0 = lane, f1 = lane + 32;

    {   // cooperative duplicated transpose of W2 into smem
        int fl = tid & 63;
        for (int j = tid >> 6; j < FF; j += 4) {
            float w = W2[j * FF + fl];
            w2d[fl * 66 + j] = make_float2(w, w);
        }
    }
    unsigned long long w1p[NBB], b1p;
#pragma unroll
    for (int i = 0; i < NBB; i++) w1p[i] = pack2(W1[i * FF + f0], W1[i * FF + f1]);
    b1p = pack2(B1[f0], B1[f1]);
    __syncthreads();

    int count = g_count;
    int stride = gridDim.x * 64;

    // prologue: prefetch trip 0 into stage 0
    {
        int slot = blockIdx.x * 64 + warp * 8 + lane;
        if (lane < 8 && slot < count) {
            const float* src = &g_ef[slot * 16];
            unsigned d = smem_u32(efb + ((0 * 8 + warp) * 8 + lane) * 4);
            cp16(d, src); cp16(d + 16, src + 4);
            cp16(d + 32, src + 8); cp16(d + 48, src + 12);
            cp8(smem_u32(idb + (0 * 8 + warp) * 8 + lane), &g_aidx[slot]);
        }
        CP_COMMIT();
    }

    int sb = 0;
    for (int tb = blockIdx.x * 64; tb < count; tb += stride) {
        int base = tb + warp * 8;
        CP_WAIT0();
        __syncwarp();
        // prefetch next trip into the other stage
        {
            int slot = tb + stride + warp * 8 + lane;
            int ns = sb ^ 1;
            if (lane < 8 && slot < count) {
                const float* src = &g_ef[slot * 16];
                unsigned d = smem_u32(efb + ((ns * 8 + warp) * 8 + lane) * 4);
                cp16(d, src); cp16(d + 16, src + 4);
                cp16(d + 32, src + 8); cp16(d + 48, src + 12);
                cp8(smem_u32(idb + (ns * 8 + warp) * 8 + lane), &g_aidx[slot]);
            }
            CP_COMMIT();
        }
        // phase 1: hidden pairs for 8 edges; all-FFMA2 (ef pre-duplicated)
#pragma unroll
        for (int ep = 0; ep < 4; ep++) {
            float ha[2], hb[2];
#pragma unroll
            for (int h = 0; h < 2; h++) {
                int e = ep * 2 + h;
                const ulonglong2* efp =
                    (const ulonglong2*)(efb + ((sb * 8 + warp) * 8 + e) * 4);
                ulonglong2 p0 = efp[0], p1 = efp[1], p2 = efp[2], p3 = efp[3];
                unsigned long long acc = b1p;
                ffma2(acc, p0.x, w1p[0]); ffma2(acc, p0.y, w1p[1]);
                ffma2(acc, p1.x, w1p[2]); ffma2(acc, p1.y, w1p[3]);
                ffma2(acc, p2.x, w1p[4]); ffma2(acc, p2.y, w1p[5]);
                ffma2(acc, p3.x, w1p[6]); ffma2(acc, p3.y, w1p[7]);
                float2 av = unpack2(acc);
                ha[h] = __fdividef(av.x, 1.0f + __expf(-av.x));   // silu f0
                hb[h] = __fdividef(av.y, 1.0f + __expf(-av.y));   // silu f1
            }
            hp[(warp * 4 + ep) * 64 + f0] = make_float2(ha[0], ha[1]);
            hp[(warp * 4 + ep) * 64 + f1] = make_float2(hb[0], hb[1]);
        }
        __syncwarp();
        // phase 2: A[ep] = (R[2ep], R[2ep+1]) via FFMA2; operands straight
        // from smem: w LDS.128 (two dup pairs), h LDS.128 (two edge pairs).
        unsigned long long A0[4], A1[4];
#pragma unroll
        for (int ep = 0; ep < 4; ep++) { A0[ep] = 0ull; A1[ep] = 0ull; }
#pragma unroll
        for (int j2 = 0; j2 < 32; j2++) {
            ulonglong2 wl = *(const ulonglong2*)(w2d + f0 * 66 + 2 * j2);
            ulonglong2 wh = *(const ulonglong2*)(w2d + f1 * 66 + 2 * j2);
#pragma unroll
            for (int ep = 0; ep < 4; ep++) {
                ulonglong2 h2 =
                    *(const ulonglong2*)(hp + (warp * 4 + ep) * 64 + 2 * j2);
                ffma2(A0[ep], h2.x, wl.x); ffma2(A0[ep], h2.y, wl.y);
                ffma2(A1[ep], h2.x, wh.x); ffma2(A1[ep], h2.y, wh.y);
            }
        }
        // phase 3: gather sc[snd], scatter messages to agg[rcv]
#pragma unroll
        for (int ep = 0; ep < 4; ep++) {
            float2 R0 = unpack2(A0[ep]);
            float2 R1 = unpack2(A1[ep]);
#pragma unroll
            for (int h = 0; h < 2; h++) {
                int slot = base + ep * 2 + h;
                if (slot < count) {
                    int2 sr = idb[(sb * 8 + warp) * 8 + ep * 2 + h];
                    float r0 = h ? R0.y : R0.x;
                    float r1 = h ? R1.y : R1.x;
                    float s0 = __ldg(&g_sc[sr.x * FF + f0]);
                    float s1 = __ldg(&g_sc[sr.x * FF + f1]);
                    atomicAdd(&g_agg[sr.y * FF + f0], r0 * s0);
                    atomicAdd(&g_agg[sr.y * FF + f1], r1 * s1);
                }
            }
        }
        __syncwarp();
        sb ^= 1;
    }
    CP_WAIT0();
}

// ---------------- K5: node update (4 nodes/block, fused reductions) ----------
__global__ void __launch_bounds__(256)
k_node_update(const float* __restrict__ attrs,
              const int*   __restrict__ batch,
              const float* __restrict__ PW,    // prod_w[l]  [10,64]
              const float* __restrict__ CW,    // charge_w[l][64]
              const float* __restrict__ ROW,   // readout_w[l][64] (l==0)
              const float* __restrict__ RW1,   // ro2_w1 [64,16]
              const float* __restrict__ RB1,   // ro2_b1 [16]
              const float* __restrict__ RW2,   // ro2_w2 [16]
              float* __restrict__ out,
              int last, int cidx) {
    int lg = threadIdx.x >> 6;
    int f  = threadIdx.x & 63;
    int n  = blockIdx.x * 4 + lg;
    __shared__ float at[4][NELS];
    __shared__ float scsm[4][FF];
    __shared__ float redc[4][FF];
    __shared__ float rede[4][FF];
    __shared__ float resc[4], rese[4];
    if (f < NELS) at[lg][f] = attrs[n * NELS + f];
    __syncthreads();
    float a = g_agg[n * FF + f] * 0.0625f;   // / AVG_NEIGH
    g_agg[n * FF + f] = 0.0f;                // pre-zero for next layer
    float pw = 0.0f;
#pragma unroll
    for (int k = 0; k < NELS; k++) pw = fmaf(at[lg][k], PW[k * FF + f], pw);
    float sc = fmaf(a, a, a) + g_sc[n * FF + f] * pw;
    g_sc[n * FF + f] = sc;
    scsm[lg][f] = sc;
    redc[lg][f] = sc * CW[f];
    if (!last) rede[lg][f] = sc * ROW[f];
    __syncthreads();
    if (f < 32) {
        float vc = redc[lg][f] + redc[lg][f + 32];
        float ve = last ? 0.0f : (rede[lg][f] + rede[lg][f + 32]);
        vc += __shfl_down_sync(0xffffffffu, vc, 16);
        ve += __shfl_down_sync(0xffffffffu, ve, 16);
        vc += __shfl_down_sync(0xffffffffu, vc, 8);
        ve += __shfl_down_sync(0xffffffffu, ve, 8);
        vc += __shfl_down_sync(0xffffffffu, vc, 4);
        ve += __shfl_down_sync(0xffffffffu, ve, 4);
        vc += __shfl_down_sync(0xffffffffu, vc, 2);
        ve += __shfl_down_sync(0xffffffffu, ve, 2);
        vc += __shfl_down_sync(0xffffffffu, vc, 1);
        ve += __shfl_down_sync(0xffffffffu, ve, 1);
        if (f == 0) { resc[lg] = vc; rese[lg] = ve; }
    }
    if (last) {
        if (f < HML) {
            float acc = RB1[f];
#pragma unroll
            for (int j = 0; j < FF; j++) acc = fmaf(scsm[lg][j], RW1[j * HML + f], acc);
            float hv = __fdividef(acc, 1.0f + __expf(-acc));
            rede[lg][f] = hv * RW2[f];
        }
        __syncthreads();
        if (f == 0) {
            float v = 0.0f;
#pragma unroll
            for (int m = 0; m < HML; m++) v += rede[lg][m];
            rese[lg] = v;
        }
    }
    if (f == 0) {
        g_cd[n] += resc[lg];
        out[OUT_NE + n] += rese[lg];
        atomicAdd(&out[OUT_CONTRIB + batch[n] * 3 + cidx], rese[lg]);
    }
}

// ---------------- K6: screened Coulomb + total charge + finalize -------------
__global__ void __launch_bounds__(256)
k_coulomb(float* __restrict__ out) {
    int g = blockIdx.x >> 4;          // 16 blocks per graph
    int ipart = blockIdx.x & 15;
    __shared__ float4 pq[NGG];        // (x, y, z, q) — one LDS.128 per pair
    int base = g * NGG;
    float qpart = 0.0f;
    for (int j = threadIdx.x; j < NGG; j += 256) {
        float q = g_cd[base + j];
        qpart += q;
        float4 p4 = g_pos4[base + j];
        pq[j] = make_float4(p4.x, p4.y, p4.z, q);
    }
    __syncthreads();
    int il = ipart * 64 + (threadIdx.x & 63);
    int jc = threadIdx.x >> 6;        // 0..3
    float e = 0.0f;
    if (il < NGG) {
        float4 me = pq[il];
        float xi = me.x, yi = me.y, zi = me.z, qi = me.w;
        float acc0 = 0.0f, acc1 = 0.0f;
        for (int j = jc; j < NGG; j += 8) {
            {
                float4 v = pq[j];
                float dx = xi - v.x, dy = yi - v.y, dz = zi - v.z;
                float d2 = fmaf(dx, dx, fmaf(dy, dy, dz * dz)) + 1e-12f;
                float rinv = rsqrtf(d2);
                float r = d2 * rinv;
                acc0 = fmaf(v.w, erff(0.5f * r) * rinv, acc0);
            }
            {
                float4 v = pq[j + 4];
                float dx = xi - v.x, dy = yi - v.y, dz = zi - v.z;
                float d2 = fmaf(dx, dx, fmaf(dy, dy, dz * dz)) + 1e-12f;
                float rinv = rsqrtf(d2);
                float r = d2 * rinv;
                acc1 = fmaf(v.w, erff(0.5f * r) * rinv, acc1);
            }
        }
        float acc = acc0 + acc1;
        if ((il & 3) == jc) {
            float rinv = rsqrtf(1e-12f);
            float r = 1e-12f * rinv;
            acc -= qi * erff(0.5f * r) * rinv;     // subtract self term
        }
        e = 0.5f * qi * acc;
    }
    // block reduce e (and qpart)
    __shared__ float wred[8], wq[8];
    float v = e, q = qpart;
    v += __shfl_down_sync(0xffffffffu, v, 16);
    q += __shfl_down_sync(0xffffffffu, q, 16);
    v += __shfl_down_sync(0xffffffffu, v, 8);
    q += __shfl_down_sync(0xffffffffu, q, 8);
    v += __shfl_down_sync(0xffffffffu, v, 4);
    q += __shfl_down_sync(0xffffffffu, q, 4);
    v += __shfl_down_sync(0xffffffffu, v, 2);
    q += __shfl_down_sync(0xffffffffu, q, 2);
    v += __shfl_down_sync(0xffffffffu, v, 1);
    q += __shfl_down_sync(0xffffffffu, q, 1);
    if ((threadIdx.x & 31) == 0) { wred[threadIdx.x >> 5] = v; wq[threadIdx.x >> 5] = q; }
    __syncthreads();
    if (threadIdx.x == 0) {
        float s = 0.0f, qsum = 0.0f;
#pragma unroll
        for (int w = 0; w < 8; w++) { s += wred[w]; qsum += wq[w]; }
        if (ipart == 0) {
            out[OUT_TC + g] = qsum;
            s += out[OUT_CONTRIB + g * 3 + 0]
               + out[OUT_CONTRIB + g * 3 + 1]
               + out[OUT_CONTRIB + g * 3 + 2];
        }
        atomicAdd(&out[OUT_TE + g], s);
    }
}

// ---------------- launch ----------------
extern "C" void kernel_launch(void* const* d_in, const int* in_sizes, int n_in,
                              void* d_out, int out_size) {
    const float* node_attrs = (const float*)d_in[0];   // [N,10]
    const float* positions  = (const float*)d_in[1];   // [N,3]
    const int*   edge_index = (const int*)d_in[2];     // [2,E]
    const int*   batch      = (const int*)d_in[3];     // [N]
    int p = (in_sizes[4] == NELS) ? 4 : 5;
    const float* atomic_energies = (const float*)d_in[p + 0];   // [10]
    const float* embed_w         = (const float*)d_in[p + 1];   // [10,64]
    const float* radial_w1       = (const float*)d_in[p + 2];   // [2,8,64]
    const float* radial_b1       = (const float*)d_in[p + 3];   // [2,64]
    const float* radial_w2       = (const float*)d_in[p + 4];   // [2,64,64]
    const float* prod_w          = (const float*)d_in[p + 5];   // [2,10,64]
    const float* readout_w       = (const float*)d_in[p + 6];   // [2,64]
    const float* ro2_w1          = (const float*)d_in[p + 7];   // [64,16]
    const float* ro2_b1          = (const float*)d_in[p + 8];   // [16]
    const float* ro2_w2          = (const float*)d_in[p + 9];   // [16]
    const float* charge_w        = (const float*)d_in[p + 10];  // [2,64]
    const float* flux_w          = (const float*)d_in[p + 11];  // [2,8]
    const float* formal_charges  = (const float*)d_in[p + 12];  // [10]
    float* out = (float*)d_out;

    cudaFuncSetAttribute(k_edge_mlp,
                         cudaFuncAttributeMaxDynamicSharedMemorySize, MLP_SMEM);

    k_zero<<<1, 256>>>(out);
    k_node_init<<<NN / 4, 256>>>(node_attrs, positions, batch,
                                 atomic_energies, embed_w, formal_charges, out);
    k_edge_geom<<<EE / 256, 256>>>(edge_index, batch, flux_w, out);

    for (int l = 0; l < 2; l++) {
        k_edge_mlp<<<444, 256, MLP_SMEM>>>(radial_w1 + l * NBB * FF,
                                           radial_b1 + l * FF,
                                           radial_w2 + l * FF * FF);
        k_node_update<<<NN / 4, 256>>>(node_attrs, batch,
                                       prod_w + l * NELS * FF,
                                       charge_w + l * FF,
                                       readout_w + l * FF,
                                       ro2_w1, ro2_b1, ro2_w2,
                                       out, (l == 1) ? 1 : 0, l + 1);
    }

    k_coulomb<<<GG * 16, 256>>>(out);
}

// round 8
// speedup vs baseline: 1.0698x; 1.0698x over previous
#include <cuda_runtime.h>
#include <math.h>

#define NN   20000
#define FF   64
#define EE   320000
#define GG   20
#define NGG  1000
#define NELS 10
#define NBB  8
#define RMAXF 5.0f
#define HML  16

// output layout (float32, 20160 elems):
#define OUT_TE      0        // [20]  total_energy
#define OUT_NE      20       // [20000] node_energy
#define OUT_CONTRIB 20020    // [20,3] contributions
#define OUT_POL     20080    // [20,3] pol
#define OUT_TC      20140    // [20]  total_charge
#define OUT_TOTAL   20160

// ---------------- device scratch (no allocation allowed) ----------------
__device__ float  g_sc[NN * FF];     // current node scalars
__device__ float  g_agg[NN * FF];    // per-layer aggregation (s=0 only!)
__device__ float  g_ef[EE * NBB];    // compacted active-edge radial features
__device__ int2   g_aidx[EE];        // compacted (snd, rcv)
__device__ float  g_cd[NN];          // charge density
__device__ float4 g_pos4[NN];        // padded positions (1-sector gathers)
__device__ int    g_count;           // active edge count

// ---------------- PTX helpers ----------------
__device__ __forceinline__ unsigned smem_u32(const void* p) {
    return (unsigned)__cvta_generic_to_shared(p);
}
__device__ __forceinline__ void cp16(unsigned d, const void* g) {
    asm volatile("cp.async.ca.shared.global [%0], [%1], 16;" :: "r"(d), "l"(g));
}
__device__ __forceinline__ void cp8(unsigned d, const void* g) {
    asm volatile("cp.async.ca.shared.global [%0], [%1], 8;" :: "r"(d), "l"(g));
}
#define CP_COMMIT()  asm volatile("cp.async.commit_group;" ::: "memory")
#define CP_WAIT0()   asm volatile("cp.async.wait_group 0;" ::: "memory")

__device__ __forceinline__ unsigned long long pack2(float x, float y) {
    unsigned long long r;
    asm("mov.b64 %0, {%1, %2};" : "=l"(r) : "f"(x), "f"(y));
    return r;
}
__device__ __forceinline__ void ffma2(unsigned long long& d,
                                      unsigned long long a, unsigned long long b) {
    asm("fma.rn.f32x2 %0, %1, %2, %3;" : "=l"(d) : "l"(a), "l"(b), "l"(d));
}
__device__ __forceinline__ float2 unpack2(unsigned long long v) {
    float2 r;
    asm("mov.b64 {%0, %1}, %2;" : "=f"(r.x), "=f"(r.y) : "l"(v));
    return r;
}

// ---------------- K0: zero small accumulator regions ----------------
__global__ void k_zero(float* __restrict__ out) {
    int i = threadIdx.x;
    if (i < GG) out[OUT_TE + i] = 0.0f;                         // total_energy
    if (i < 140) out[OUT_CONTRIB + i] = 0.0f;                   // contrib+pol+tc
    if (i == 0) g_count = 0;
}

// ---------------- K1: node init (embed, E0, FQ, pol, pos4; 4 nodes/block) ---
__global__ void __launch_bounds__(256)
k_node_init(const float* __restrict__ attrs,
            const float* __restrict__ pos,
            const int*   __restrict__ batch,
            const float* __restrict__ ae,
            const float* __restrict__ embw,
            const float* __restrict__ fc,
            float* __restrict__ out) {
    int lg = threadIdx.x >> 6;
    int f  = threadIdx.x & 63;
    int n  = blockIdx.x * 4 + lg;
    __shared__ float at[4][NELS];
    __shared__ float fqs[4];
    if (f < NELS) at[lg][f] = attrs[n * NELS + f];
    __syncthreads();
    float s = 0.0f;
#pragma unroll
    for (int k = 0; k < NELS; k++) s = fmaf(at[lg][k], embw[k * FF + f], s);
    g_sc[n * FF + f] = s;
    g_agg[n * FF + f] = 0.0f;
    if (f == 0) {
        float fq = 0.0f, ne0 = 0.0f;
#pragma unroll
        for (int k = 0; k < NELS; k++) { fq = fmaf(at[lg][k], fc[k], fq); ne0 = fmaf(at[lg][k], ae[k], ne0); }
        g_cd[n] = fq;
        out[OUT_NE + n] = ne0;
        atomicAdd(&out[OUT_CONTRIB + batch[n] * 3 + 0], ne0);
        fqs[lg] = fq;
        g_pos4[n] = make_float4(pos[n * 3 + 0], pos[n * 3 + 1], pos[n * 3 + 2], 0.0f);
    }
    __syncthreads();
    if (f < 3)
        atomicAdd(&out[OUT_POL + batch[n] * 3 + f], fqs[lg] * pos[n * 3 + f]);
}

// ---------------- K2: edge geometry + radial basis + flux/pol + compaction ---
__global__ void __launch_bounds__(256)
k_edge_geom(const int*   __restrict__ ei,
            const int*   __restrict__ batch,
            const float* __restrict__ fw,   // flux_w [2,8]
            float* __restrict__ out) {
    int e = blockIdx.x * 256 + threadIdx.x;    // grid sized exactly EE/256
    int lane = threadIdx.x & 31;
    __shared__ float polsm[GG * 3];
    if (threadIdx.x < GG * 3) polsm[threadIdx.x] = 0.0f;
    __syncthreads();

    int snd = ei[e], rcv = ei[EE + e];
    float4 ps = g_pos4[snd], pr = g_pos4[rcv];
    float dx = pr.x - ps.x, dy = pr.y - ps.y, dz = pr.z - ps.z;
    float d2 = fmaf(dx, dx, fmaf(dy, dy, dz * dz)) + 1e-12f;
    float rinv = rsqrtf(d2);
    float r = d2 * rinv;
    bool active = (r < RMAXF);
    float ef[NBB];
    float flux = 0.0f;
    if (active) {
        float x = r * (1.0f / RMAXF);
        float x2 = x * x;
        float x5 = x2 * x2 * x;
        float u = 1.0f + x5 * (-21.0f + x * (35.0f - 15.0f * x));
        float pref = 0.6324555320336759f * u * rinv;    // sqrt(2/5)*u/r
        float s1, c1;
        __sincosf(r * 0.6283185307179586f, &s1, &c1);   // pi/5 * r
        float sn = s1, cn = c1;
#pragma unroll
        for (int i = 0; i < NBB; i++) {
            float v = pref * sn;
            ef[i] = v;
            flux = fmaf(v, fw[i] + fw[NBB + i], flux);
            float sn2 = sn * c1 + cn * s1;
            cn = cn * c1 - sn * s1;
            sn = sn2;
        }
    }

    unsigned mask = __ballot_sync(0xffffffffu, active);
    if (mask) {
        int leader = __ffs(mask) - 1;
        int cnt = __popc(mask);
        int base = 0;
        if (lane == leader) base = atomicAdd(&g_count, cnt);
        base = __shfl_sync(0xffffffffu, base, leader);
        if (active) {
            int slot = base + __popc(mask & ((1u << lane) - 1u));
            float4* ef4 = (float4*)&g_ef[slot * NBB];
            ef4[0] = make_float4(ef[0], ef[1], ef[2], ef[3]);
            ef4[1] = make_float4(ef[4], ef[5], ef[6], ef[7]);
            g_aidx[slot] = make_int2(snd, rcv);
            int g = batch[rcv];
            atomicAdd(&polsm[g * 3 + 0], flux * dx);
            atomicAdd(&polsm[g * 3 + 1], flux * dy);
            atomicAdd(&polsm[g * 3 + 2], flux * dz);
        }
    }
    __syncthreads();
    if (threadIdx.x < GG * 3) {
        float v = polsm[threadIdx.x];
        if (v != 0.0f) atomicAdd(&out[OUT_POL + threadIdx.x], v);
    }
}

// ---------------- K4: per-edge radial MLP + message scatter (s=0 only) -------
// R6 design (proven fastest) + ulonglong2 broadcast h-loads in phase 2.
__global__ void __launch_bounds__(256, 3)
k_edge_mlp(const float* __restrict__ W1,   // [8,64]
           const float* __restrict__ B1,   // [64]
           const float* __restrict__ W2) { // [64,64]
    __shared__ float4 w2t4[FF][17];        // w2t4[f][j4] = W2[4j4..4j4+3][f]
    __shared__ float2 hp[8][4][FF];        // [warp][edge-pair][hidden j]
    __shared__ float4 efb[2][8][8][2];     // [stage][warp][edge][2xfloat4]
    __shared__ int2   idb[2][8][8];        // [stage][warp][edge]
    int tid = threadIdx.x;
    int warp = tid >> 5;
    int lane = tid & 31;
    int f0 = lane, f1 = lane + 32;

    {   // cooperative transpose of W2 into smem
        int fl = tid & 63;
        int q  = tid >> 6;
        float* w2s = (float*)w2t4;         // row stride 68 floats
        for (int j = q; j < FF; j += 4) w2s[fl * 68 + j] = W2[j * FF + fl];
    }
    float w1a[NBB], w1b[NBB];
#pragma unroll
    for (int i = 0; i < NBB; i++) { w1a[i] = W1[i * FF + f0]; w1b[i] = W1[i * FF + f1]; }
    float b1a = B1[f0], b1b = B1[f1];
    __syncthreads();

    int count = g_count;
    int stride = gridDim.x * 64;

    // prologue: prefetch trip 0 into stage 0
    {
        int slot = blockIdx.x * 64 + warp * 8 + lane;
        if (lane < 8 && slot < count) {
            cp16(smem_u32(&efb[0][warp][lane][0]), &g_ef[slot * NBB]);
            cp16(smem_u32(&efb[0][warp][lane][1]), &g_ef[slot * NBB + 4]);
            cp8(smem_u32(&idb[0][warp][lane]), &g_aidx[slot]);
        }
        CP_COMMIT();
    }

    int sb = 0;
    for (int tb = blockIdx.x * 64; tb < count; tb += stride) {
        int base = tb + warp * 8;
        CP_WAIT0();
        __syncwarp();
        // prefetch next trip into the other stage
        {
            int slot = tb + stride + warp * 8 + lane;
            if (lane < 8 && slot < count) {
                cp16(smem_u32(&efb[sb ^ 1][warp][lane][0]), &g_ef[slot * NBB]);
                cp16(smem_u32(&efb[sb ^ 1][warp][lane][1]), &g_ef[slot * NBB + 4]);
                cp8(smem_u32(&idb[sb ^ 1][warp][lane]), &g_aidx[slot]);
            }
            CP_COMMIT();
        }
        // phase 1: hidden activations for 8 edges (this lane's 2 hidden units)
#pragma unroll
        for (int e = 0; e < 8; e++) {
            int slot = base + e;
            float h0 = 0.0f, h1 = 0.0f;
            if (slot < count) {
                float4 a = efb[sb][warp][e][0];
                float4 b = efb[sb][warp][e][1];
                float acc0 = b1a, acc1 = b1b;
                acc0 = fmaf(a.x, w1a[0], acc0); acc1 = fmaf(a.x, w1b[0], acc1);
                acc0 = fmaf(a.y, w1a[1], acc0); acc1 = fmaf(a.y, w1b[1], acc1);
                acc0 = fmaf(a.z, w1a[2], acc0); acc1 = fmaf(a.z, w1b[2], acc1);
                acc0 = fmaf(a.w, w1a[3], acc0); acc1 = fmaf(a.w, w1b[3], acc1);
                acc0 = fmaf(b.x, w1a[4], acc0); acc1 = fmaf(b.x, w1b[4], acc1);
                acc0 = fmaf(b.y, w1a[5], acc0); acc1 = fmaf(b.y, w1b[5], acc1);
                acc0 = fmaf(b.z, w1a[6], acc0); acc1 = fmaf(b.z, w1b[6], acc1);
                acc0 = fmaf(b.w, w1a[7], acc0); acc1 = fmaf(b.w, w1b[7], acc1);
                h0 = __fdividef(acc0, 1.0f + __expf(-acc0));     // silu (MUFU)
                h1 = __fdividef(acc1, 1.0f + __expf(-acc1));
            }
            ((float*)&hp[warp][e >> 1][f0])[e & 1] = h0;
            ((float*)&hp[warp][e >> 1][f1])[e & 1] = h1;
        }
        __syncwarp();
        // phase 2: packed f32x2 GEMM; h loaded as ulonglong2 (LDS.128
        // broadcast, two j's per load), w packed once per j.
        unsigned long long A0[4], A1[4];
#pragma unroll
        for (int ep = 0; ep < 4; ep++) { A0[ep] = 0ull; A1[ep] = 0ull; }
#pragma unroll
        for (int j4 = 0; j4 < 16; j4++) {
            float4 wl4 = w2t4[f0][j4];
            float4 wh4 = w2t4[f1][j4];
            unsigned long long pwl0 = pack2(wl4.x, wl4.x);
            unsigned long long pwl1 = pack2(wl4.y, wl4.y);
            unsigned long long pwl2 = pack2(wl4.z, wl4.z);
            unsigned long long pwl3 = pack2(wl4.w, wl4.w);
            unsigned long long pwh0 = pack2(wh4.x, wh4.x);
            unsigned long long pwh1 = pack2(wh4.y, wh4.y);
            unsigned long long pwh2 = pack2(wh4.z, wh4.z);
            unsigned long long pwh3 = pack2(wh4.w, wh4.w);
#pragma unroll
            for (int ep = 0; ep < 4; ep++) {
                ulonglong2 hA = *(const ulonglong2*)&hp[warp][ep][j4 * 4];      // j0,j1
                ulonglong2 hB = *(const ulonglong2*)&hp[warp][ep][j4 * 4 + 2];  // j2,j3
                ffma2(A0[ep], hA.x, pwl0); ffma2(A1[ep], hA.x, pwh0);
                ffma2(A0[ep], hA.y, pwl1); ffma2(A1[ep], hA.y, pwh1);
                ffma2(A0[ep], hB.x, pwl2); ffma2(A1[ep], hB.x, pwh2);
                ffma2(A0[ep], hB.y, pwl3); ffma2(A1[ep], hB.y, pwh3);
            }
        }
        // phase 3: gather sc[snd], scatter messages to agg[rcv]
#pragma unroll
        for (int ep = 0; ep < 4; ep++) {
            float2 R0 = unpack2(A0[ep]);
            float2 R1 = unpack2(A1[ep]);
#pragma unroll
            for (int h = 0; h < 2; h++) {
                int slot = base + ep * 2 + h;
                if (slot < count) {
                    int2 sr = idb[sb][warp][ep * 2 + h];
                    float r0 = h ? R0.y : R0.x;
                    float r1 = h ? R1.y : R1.x;
                    float s0 = __ldg(&g_sc[sr.x * FF + f0]);
                    float s1 = __ldg(&g_sc[sr.x * FF + f1]);
                    atomicAdd(&g_agg[sr.y * FF + f0], r0 * s0);
                    atomicAdd(&g_agg[sr.y * FF + f1], r1 * s1);
                }
            }
        }
        __syncwarp();
        sb ^= 1;
    }
    CP_WAIT0();
}

// ---------------- K5: node update (4 nodes/block, fused reductions) ----------
__global__ void __launch_bounds__(256)
k_node_update(const float* __restrict__ attrs,
              const int*   __restrict__ batch,
              const float* __restrict__ PW,    // prod_w[l]  [10,64]
              const float* __restrict__ CW,    // charge_w[l][64]
              const float* __restrict__ ROW,   // readout_w[l][64] (l==0)
              const float* __restrict__ RW1,   // ro2_w1 [64,16]
              const float* __restrict__ RB1,   // ro2_b1 [16]
              const float* __restrict__ RW2,   // ro2_w2 [16]
              float* __restrict__ out,
              int last, int cidx) {
    int lg = threadIdx.x >> 6;
    int f  = threadIdx.x & 63;
    int n  = blockIdx.x * 4 + lg;
    __shared__ float at[4][NELS];
    __shared__ float scsm[4][FF];
    __shared__ float redc[4][FF];
    __shared__ float rede[4][FF];
    __shared__ float resc[4], rese[4];
    if (f < NELS) at[lg][f] = attrs[n * NELS + f];
    __syncthreads();
    float a = g_agg[n * FF + f] * 0.0625f;   // / AVG_NEIGH
    g_agg[n * FF + f] = 0.0f;                // pre-zero for next layer
    float pw = 0.0f;
#pragma unroll
    for (int k = 0; k < NELS; k++) pw = fmaf(at[lg][k], PW[k * FF + f], pw);
    float sc = fmaf(a, a, a) + g_sc[n * FF + f] * pw;
    g_sc[n * FF + f] = sc;
    scsm[lg][f] = sc;
    redc[lg][f] = sc * CW[f];
    if (!last) rede[lg][f] = sc * ROW[f];
    __syncthreads();
    if (f < 32) {
        float vc = redc[lg][f] + redc[lg][f + 32];
        float ve = last ? 0.0f : (rede[lg][f] + rede[lg][f + 32]);
        vc += __shfl_down_sync(0xffffffffu, vc, 16);
        ve += __shfl_down_sync(0xffffffffu, ve, 16);
        vc += __shfl_down_sync(0xffffffffu, vc, 8);
        ve += __shfl_down_sync(0xffffffffu, ve, 8);
        vc += __shfl_down_sync(0xffffffffu, vc, 4);
        ve += __shfl_down_sync(0xffffffffu, ve, 4);
        vc += __shfl_down_sync(0xffffffffu, vc, 2);
        ve += __shfl_down_sync(0xffffffffu, ve, 2);
        vc += __shfl_down_sync(0xffffffffu, vc, 1);
        ve += __shfl_down_sync(0xffffffffu, ve, 1);
        if (f == 0) { resc[lg] = vc; rese[lg] = ve; }
    }
    if (last) {
        if (f < HML) {
            float acc = RB1[f];
#pragma unroll
            for (int j = 0; j < FF; j++) acc = fmaf(scsm[lg][j], RW1[j * HML + f], acc);
            float hv = __fdividef(acc, 1.0f + __expf(-acc));
            rede[lg][f] = hv * RW2[f];
        }
        __syncthreads();
        if (f == 0) {
            float v = 0.0f;
#pragma unroll
            for (int m = 0; m < HML; m++) v += rede[lg][m];
            rese[lg] = v;
        }
    }
    if (f == 0) {
        g_cd[n] += resc[lg];
        out[OUT_NE + n] += rese[lg];
        atomicAdd(&out[OUT_CONTRIB + batch[n] * 3 + cidx], rese[lg]);
    }
}

// ---------------- K6: screened Coulomb + total charge + finalize -------------
__global__ void __launch_bounds__(256)
k_coulomb(float* __restrict__ out) {
    int g = blockIdx.x >> 4;          // 16 blocks per graph
    int ipart = blockIdx.x & 15;
    __shared__ float4 pq[NGG];        // (x, y, z, q) — one LDS.128 per pair
    int base = g * NGG;
    float qpart = 0.0f;
    for (int j = threadIdx.x; j < NGG; j += 256) {
        float q = g_cd[base + j];
        qpart += q;
        float4 p4 = g_pos4[base + j];
        pq[j] = make_float4(p4.x, p4.y, p4.z, q);
    }
    __syncthreads();
    int il = ipart * 64 + (threadIdx.x & 63);
    int jc = threadIdx.x >> 6;        // 0..3
    float e = 0.0f;
    if (il < NGG) {
        float4 me = pq[il];
        float xi = me.x, yi = me.y, zi = me.z, qi = me.w;
        float acc0 = 0.0f, acc1 = 0.0f;
        for (int j = jc; j < NGG; j += 8) {
            {
                float4 v = pq[j];
                float dx = xi - v.x, dy = yi - v.y, dz = zi - v.z;
                float d2 = fmaf(dx, dx, fmaf(dy, dy, dz * dz)) + 1e-12f;
                float rinv = rsqrtf(d2);
                float r = d2 * rinv;
                acc0 = fmaf(v.w, erff(0.5f * r) * rinv, acc0);
            }
            {
                float4 v = pq[j + 4];
                float dx = xi - v.x, dy = yi - v.y, dz = zi - v.z;
                float d2 = fmaf(dx, dx, fmaf(dy, dy, dz * dz)) + 1e-12f;
                float rinv = rsqrtf(d2);
                float r = d2 * rinv;
                acc1 = fmaf(v.w, erff(0.5f * r) * rinv, acc1);
            }
        }
        float acc = acc0 + acc1;
        if ((il & 3) == jc) {
            float rinv = rsqrtf(1e-12f);
            float r = 1e-12f * rinv;
            acc -= qi * erff(0.5f * r) * rinv;     // subtract self term
        }
        e = 0.5f * qi * acc;
    }
    // block reduce e (and qpart)
    __shared__ float wred[8], wq[8];
    float v = e, q = qpart;
    v += __shfl_down_sync(0xffffffffu, v, 16);
    q += __shfl_down_sync(0xffffffffu, q, 16);
    v += __shfl_down_sync(0xffffffffu, v, 8);
    q += __shfl_down_sync(0xffffffffu, q, 8);
    v += __shfl_down_sync(0xffffffffu, v, 4);
    q += __shfl_down_sync(0xffffffffu, q, 4);
    v += __shfl_down_sync(0xffffffffu, v, 2);
    q += __shfl_down_sync(0xffffffffu, q, 2);
    v += __shfl_down_sync(0xffffffffu, v, 1);
    q += __shfl_down_sync(0xffffffffu, q, 1);
    if ((threadIdx.x & 31) == 0) { wred[threadIdx.x >> 5] = v; wq[threadIdx.x >> 5] = q; }
    __syncthreads();
    if (threadIdx.x == 0) {
        float s = 0.0f, qsum = 0.0f;
#pragma unroll
        for (int w = 0; w < 8; w++) { s += wred[w]; qsum += wq[w]; }
        if (ipart == 0) {
            out[OUT_TC + g] = qsum;
            s += out[OUT_CONTRIB + g * 3 + 0]
               + out[OUT_CONTRIB + g * 3 + 1]
               + out[OUT_CONTRIB + g * 3 + 2];
        }
        atomicAdd(&out[OUT_TE + g], s);
    }
}

// ---------------- launch ----------------
extern "C" void kernel_launch(void* const* d_in, const int* in_sizes, int n_in,
                              void* d_out, int out_size) {
    const float* node_attrs = (const float*)d_in[0];   // [N,10]
    const float* positions  = (const float*)d_in[1];   // [N,3]
    const int*   edge_index = (const int*)d_in[2];     // [2,E]
    const int*   batch      = (const int*)d_in[3];     // [N]
    int p = (in_sizes[4] == NELS) ? 4 : 5;
    const float* atomic_energies = (const float*)d_in[p + 0];   // [10]
    const float* embed_w         = (const float*)d_in[p + 1];   // [10,64]
    const float* radial_w1       = (const float*)d_in[p + 2];   // [2,8,64]
    const float* radial_b1       = (const float*)d_in[p + 3];   // [2,64]
    const float* radial_w2       = (const float*)d_in[p + 4];   // [2,64,64]
    const float* prod_w          = (const float*)d_in[p + 5];   // [2,10,64]
    const float* readout_w       = (const float*)d_in[p + 6];   // [2,64]
    const float* ro2_w1          = (const float*)d_in[p + 7];   // [64,16]
    const float* ro2_b1          = (const float*)d_in[p + 8];   // [16]
    const float* ro2_w2          = (const float*)d_in[p + 9];   // [16]
    const float* charge_w        = (const float*)d_in[p + 10];  // [2,64]
    const float* flux_w          = (const float*)d_in[p + 11];  // [2,8]
    const float* formal_charges  = (const float*)d_in[p + 12];  // [10]
    float* out = (float*)d_out;

    k_zero<<<1, 256>>>(out);
    k_node_init<<<NN / 4, 256>>>(node_attrs, positions, batch,
                                 atomic_energies, embed_w, formal_charges, out);
    k_edge_geom<<<EE / 256, 256>>>(edge_index, batch, flux_w, out);

    for (int l = 0; l < 2; l++) {
        k_edge_mlp<<<444, 256>>>(radial_w1 + l * NBB * FF,
                                 radial_b1 + l * FF,
                                 radial_w2 + l * FF * FF);
        k_node_update<<<NN / 4, 256>>>(node_attrs, batch,
                                       prod_w + l * NELS * FF,
                                       charge_w + l * FF,
                                       readout_w + l * FF,
                                       ro2_w1, ro2_b1, ro2_w2,
                                       out, (l == 1) ? 1 : 0, l + 1);
    }

    k_coulomb<<<GG * 16, 256>>>(out);
}

// round 9
// speedup vs baseline: 1.0814x; 1.0108x over previous
#include <cuda_runtime.h>
#include <math.h>

#define NN   20000
#define FF   64
#define EE   320000
#define GG   20
#define NGG  1000
#define NELS 10
#define NBB  8
#define RMAXF 5.0f
#define HML  16

// output layout (float32, 20160 elems):
#define OUT_TE      0        // [20]  total_energy
#define OUT_NE      20       // [20000] node_energy
#define OUT_CONTRIB 20020    // [20,3] contributions
#define OUT_POL     20080    // [20,3] pol
#define OUT_TC      20140    // [20]  total_charge
#define OUT_TOTAL   20160

// ---------------- device scratch (no allocation allowed) ----------------
__device__ float  g_sc[NN * FF];     // current node scalars
__device__ float  g_agg[NN * FF];    // per-layer aggregation (s=0 only!)
__device__ float  g_ef[EE * NBB];    // compacted active-edge radial features
__device__ int2   g_aidx[EE];        // compacted (snd, rcv)
__device__ float  g_cd[NN];          // charge density
__device__ float4 g_pos4[NN];        // padded positions (1-sector gathers)
__device__ int    g_count;           // active edge count

// ---------------- PTX helpers ----------------
__device__ __forceinline__ unsigned smem_u32(const void* p) {
    return (unsigned)__cvta_generic_to_shared(p);
}
__device__ __forceinline__ void cp16(unsigned d, const void* g) {
    asm volatile("cp.async.ca.shared.global [%0], [%1], 16;" :: "r"(d), "l"(g));
}
__device__ __forceinline__ void cp8(unsigned d, const void* g) {
    asm volatile("cp.async.ca.shared.global [%0], [%1], 8;" :: "r"(d), "l"(g));
}
#define CP_COMMIT()  asm volatile("cp.async.commit_group;" ::: "memory")
#define CP_WAIT0()   asm volatile("cp.async.wait_group 0;" ::: "memory")

__device__ __forceinline__ unsigned long long pack2(float x, float y) {
    unsigned long long r;
    asm("mov.b64 %0, {%1, %2};" : "=l"(r) : "f"(x), "f"(y));
    return r;
}
__device__ __forceinline__ void ffma2(unsigned long long& d,
                                      unsigned long long a, unsigned long long b) {
    asm("fma.rn.f32x2 %0, %1, %2, %3;" : "=l"(d) : "l"(a), "l"(b), "l"(d));
}
__device__ __forceinline__ float2 unpack2(unsigned long long v) {
    float2 r;
    asm("mov.b64 {%0, %1}, %2;" : "=f"(r.x), "=f"(r.y) : "l"(v));
    return r;
}
// vector reduction: one REDG.64 for two adjacent floats (sm_90+)
__device__ __forceinline__ void red_v2(float* p, float a, float b) {
    asm volatile("red.global.add.v2.f32 [%0], {%1, %2};"
                 :: "l"(p), "f"(a), "f"(b) : "memory");
}

// ---------------- K0: zero small accumulator regions ----------------
__global__ void k_zero(float* __restrict__ out) {
    int i = threadIdx.x;
    if (i < GG) out[OUT_TE + i] = 0.0f;                         // total_energy
    if (i < 140) out[OUT_CONTRIB + i] = 0.0f;                   // contrib+pol+tc
    if (i == 0) g_count = 0;
}

// ---------------- K1: node init (embed, E0, FQ, pol, pos4; 4 nodes/block) ---
__global__ void __launch_bounds__(256)
k_node_init(const float* __restrict__ attrs,
            const float* __restrict__ pos,
            const int*   __restrict__ batch,
            const float* __restrict__ ae,
            const float* __restrict__ embw,
            const float* __restrict__ fc,
            float* __restrict__ out) {
    int lg = threadIdx.x >> 6;
    int f  = threadIdx.x & 63;
    int n  = blockIdx.x * 4 + lg;
    __shared__ float at[4][NELS];
    __shared__ float fqs[4];
    if (f < NELS) at[lg][f] = attrs[n * NELS + f];
    __syncthreads();
    float s = 0.0f;
#pragma unroll
    for (int k = 0; k < NELS; k++) s = fmaf(at[lg][k], embw[k * FF + f], s);
    g_sc[n * FF + f] = s;
    g_agg[n * FF + f] = 0.0f;
    if (f == 0) {
        float fq = 0.0f, ne0 = 0.0f;
#pragma unroll
        for (int k = 0; k < NELS; k++) { fq = fmaf(at[lg][k], fc[k], fq); ne0 = fmaf(at[lg][k], ae[k], ne0); }
        g_cd[n] = fq;
        out[OUT_NE + n] = ne0;
        atomicAdd(&out[OUT_CONTRIB + batch[n] * 3 + 0], ne0);
        fqs[lg] = fq;
        g_pos4[n] = make_float4(pos[n * 3 + 0], pos[n * 3 + 1], pos[n * 3 + 2], 0.0f);
    }
    __syncthreads();
    if (f < 3)
        atomicAdd(&out[OUT_POL + batch[n] * 3 + f], fqs[lg] * pos[n * 3 + f]);
}

// ---------------- K2: edge geometry + radial basis + flux/pol + compaction ---
__global__ void __launch_bounds__(256)
k_edge_geom(const int*   __restrict__ ei,
            const int*   __restrict__ batch,
            const float* __restrict__ fw,   // flux_w [2,8]
            float* __restrict__ out) {
    int e = blockIdx.x * 256 + threadIdx.x;    // grid sized exactly EE/256
    int lane = threadIdx.x & 31;
    __shared__ float polsm[GG * 3];
    if (threadIdx.x < GG * 3) polsm[threadIdx.x] = 0.0f;
    __syncthreads();

    int snd = ei[e], rcv = ei[EE + e];
    float4 ps = g_pos4[snd], pr = g_pos4[rcv];
    float dx = pr.x - ps.x, dy = pr.y - ps.y, dz = pr.z - ps.z;
    float d2 = fmaf(dx, dx, fmaf(dy, dy, dz * dz)) + 1e-12f;
    float rinv = rsqrtf(d2);
    float r = d2 * rinv;
    bool active = (r < RMAXF);
    float ef[NBB];
    float flux = 0.0f;
    if (active) {
        float x = r * (1.0f / RMAXF);
        float x2 = x * x;
        float x5 = x2 * x2 * x;
        float u = 1.0f + x5 * (-21.0f + x * (35.0f - 15.0f * x));
        float pref = 0.6324555320336759f * u * rinv;    // sqrt(2/5)*u/r
        float s1, c1;
        __sincosf(r * 0.6283185307179586f, &s1, &c1);   // pi/5 * r
        float sn = s1, cn = c1;
#pragma unroll
        for (int i = 0; i < NBB; i++) {
            float v = pref * sn;
            ef[i] = v;
            flux = fmaf(v, fw[i] + fw[NBB + i], flux);
            float sn2 = sn * c1 + cn * s1;
            cn = cn * c1 - sn * s1;
            sn = sn2;
        }
    }

    unsigned mask = __ballot_sync(0xffffffffu, active);
    if (mask) {
        int leader = __ffs(mask) - 1;
        int cnt = __popc(mask);
        int base = 0;
        if (lane == leader) base = atomicAdd(&g_count, cnt);
        base = __shfl_sync(0xffffffffu, base, leader);
        if (active) {
            int slot = base + __popc(mask & ((1u << lane) - 1u));
            float4* ef4 = (float4*)&g_ef[slot * NBB];
            ef4[0] = make_float4(ef[0], ef[1], ef[2], ef[3]);
            ef4[1] = make_float4(ef[4], ef[5], ef[6], ef[7]);
            g_aidx[slot] = make_int2(snd, rcv);
            int g = batch[rcv];
            atomicAdd(&polsm[g * 3 + 0], flux * dx);
            atomicAdd(&polsm[g * 3 + 1], flux * dy);
            atomicAdd(&polsm[g * 3 + 2], flux * dz);
        }
    }
    __syncthreads();
    if (threadIdx.x < GG * 3) {
        float v = polsm[threadIdx.x];
        if (v != 0.0f) atomicAdd(&out[OUT_POL + threadIdx.x], v);
    }
}

// ---------------- K4: per-edge radial MLP + message scatter (s=0 only) -------
// R6/R8 design; lane owns ADJACENT features f0=2*lane, f1=2*lane+1 so the
// phase-3 gather/scatter are 64-bit (LDG.64 + red.global.add.v2.f32), halving
// global LSU ops. Hidden index permuted by pi(j)=(j>>1)+(j&1)*32 in BOTH hp
// and w2t (dot product invariant) so smem patterns stay byte-identical.
__global__ void __launch_bounds__(256, 3)
k_edge_mlp(const float* __restrict__ W1,   // [8,64]
           const float* __restrict__ B1,   // [64]
           const float* __restrict__ W2) { // [64,64]
    __shared__ float4 w2t4[FF][17];        // physical rows: pi-permuted f
    __shared__ float2 hp[8][4][FF];        // [warp][edge-pair][pi(j)]
    __shared__ float4 efb[2][8][8][2];     // [stage][warp][edge][2xfloat4]
    __shared__ int2   idb[2][8][8];        // [stage][warp][edge]
    int tid = threadIdx.x;
    int warp = tid >> 5;
    int lane = tid & 31;
    int f0 = 2 * lane, f1 = 2 * lane + 1;  // logical features of this lane

    {   // cooperative transpose of W2 into smem with pi-permuted row index:
        // physical row pi(f) = (f>>1) + (f&1)*32  ==> lane reads rows l, l+32
        int fl = tid & 63;
        int prow = (fl >> 1) + (fl & 1) * 32;
        int q  = tid >> 6;
        float* w2s = (float*)w2t4;         // row stride 68 floats
        for (int j = q; j < FF; j += 4) {
            int jp = (j >> 1) + (j & 1) * 32;     // pi on the j index too
            w2s[prow * 68 + jp] = W2[j * FF + fl];
        }
    }
    float w1a[NBB], w1b[NBB];
#pragma unroll
    for (int i = 0; i < NBB; i++) { w1a[i] = W1[i * FF + f0]; w1b[i] = W1[i * FF + f1]; }
    float b1a = B1[f0], b1b = B1[f1];
    __syncthreads();

    int count = g_count;
    int stride = gridDim.x * 64;

    // prologue: prefetch trip 0 into stage 0
    {
        int slot = blockIdx.x * 64 + warp * 8 + lane;
        if (lane < 8 && slot < count) {
            cp16(smem_u32(&efb[0][warp][lane][0]), &g_ef[slot * NBB]);
            cp16(smem_u32(&efb[0][warp][lane][1]), &g_ef[slot * NBB + 4]);
            cp8(smem_u32(&idb[0][warp][lane]), &g_aidx[slot]);
        }
        CP_COMMIT();
    }

    int sb = 0;
    for (int tb = blockIdx.x * 64; tb < count; tb += stride) {
        int base = tb + warp * 8;
        CP_WAIT0();
        __syncwarp();
        // prefetch next trip into the other stage
        {
            int slot = tb + stride + warp * 8 + lane;
            if (lane < 8 && slot < count) {
                cp16(smem_u32(&efb[sb ^ 1][warp][lane][0]), &g_ef[slot * NBB]);
                cp16(smem_u32(&efb[sb ^ 1][warp][lane][1]), &g_ef[slot * NBB + 4]);
                cp8(smem_u32(&idb[sb ^ 1][warp][lane]), &g_aidx[slot]);
            }
            CP_COMMIT();
        }
        // phase 1: hidden units f0, f1 for 8 edges; store at physical rows
        // pi(f0)=lane, pi(f1)=lane+32 (same smem pattern as before).
#pragma unroll
        for (int e = 0; e < 8; e++) {
            int slot = base + e;
            float h0 = 0.0f, h1 = 0.0f;
            if (slot < count) {
                float4 a = efb[sb][warp][e][0];
                float4 b = efb[sb][warp][e][1];
                float acc0 = b1a, acc1 = b1b;
                acc0 = fmaf(a.x, w1a[0], acc0); acc1 = fmaf(a.x, w1b[0], acc1);
                acc0 = fmaf(a.y, w1a[1], acc0); acc1 = fmaf(a.y, w1b[1], acc1);
                acc0 = fmaf(a.z, w1a[2], acc0); acc1 = fmaf(a.z, w1b[2], acc1);
                acc0 = fmaf(a.w, w1a[3], acc0); acc1 = fmaf(a.w, w1b[3], acc1);
                acc0 = fmaf(b.x, w1a[4], acc0); acc1 = fmaf(b.x, w1b[4], acc1);
                acc0 = fmaf(b.y, w1a[5], acc0); acc1 = fmaf(b.y, w1b[5], acc1);
                acc0 = fmaf(b.z, w1a[6], acc0); acc1 = fmaf(b.z, w1b[6], acc1);
                acc0 = fmaf(b.w, w1a[7], acc0); acc1 = fmaf(b.w, w1b[7], acc1);
                h0 = __fdividef(acc0, 1.0f + __expf(-acc0));     // silu (MUFU)
                h1 = __fdividef(acc1, 1.0f + __expf(-acc1));
            }
            ((float*)&hp[warp][e >> 1][lane])[e & 1] = h0;        // pi(f0)
            ((float*)&hp[warp][e >> 1][lane + 32])[e & 1] = h1;   // pi(f1)
        }
        __syncwarp();
        // phase 2: packed f32x2 GEMM over permuted hidden index (invariant).
        unsigned long long A0[4], A1[4];
#pragma unroll
        for (int ep = 0; ep < 4; ep++) { A0[ep] = 0ull; A1[ep] = 0ull; }
#pragma unroll
        for (int j4 = 0; j4 < 16; j4++) {
            float4 wl4 = w2t4[lane][j4];           // feature f0 (phys row lane)
            float4 wh4 = w2t4[lane + 32][j4];      // feature f1
            unsigned long long pwl0 = pack2(wl4.x, wl4.x);
            unsigned long long pwl1 = pack2(wl4.y, wl4.y);
            unsigned long long pwl2 = pack2(wl4.z, wl4.z);
            unsigned long long pwl3 = pack2(wl4.w, wl4.w);
            unsigned long long pwh0 = pack2(wh4.x, wh4.x);
            unsigned long long pwh1 = pack2(wh4.y, wh4.y);
            unsigned long long pwh2 = pack2(wh4.z, wh4.z);
            unsigned long long pwh3 = pack2(wh4.w, wh4.w);
#pragma unroll
            for (int ep = 0; ep < 4; ep++) {
                ulonglong2 hA = *(const ulonglong2*)&hp[warp][ep][j4 * 4];
                ulonglong2 hB = *(const ulonglong2*)&hp[warp][ep][j4 * 4 + 2];
                ffma2(A0[ep], hA.x, pwl0); ffma2(A1[ep], hA.x, pwh0);
                ffma2(A0[ep], hA.y, pwl1); ffma2(A1[ep], hA.y, pwh1);
                ffma2(A0[ep], hB.x, pwl2); ffma2(A1[ep], hB.x, pwh2);
                ffma2(A0[ep], hB.y, pwl3); ffma2(A1[ep], hB.y, pwh3);
            }
        }
        // phase 3: LDG.64 sc gather + red.v2 scatter (adjacent features)
#pragma unroll
        for (int ep = 0; ep < 4; ep++) {
            float2 R0 = unpack2(A0[ep]);   // feature f0 for edges 2ep, 2ep+1
            float2 R1 = unpack2(A1[ep]);   // feature f1
#pragma unroll
            for (int h = 0; h < 2; h++) {
                int slot = base + ep * 2 + h;
                if (slot < count) {
                    int2 sr = idb[sb][warp][ep * 2 + h];
                    float2 sv = __ldg((const float2*)&g_sc[sr.x * FF + f0]);
                    float r0 = h ? R0.y : R0.x;
                    float r1 = h ? R1.y : R1.x;
                    red_v2(&g_agg[sr.y * FF + f0], r0 * sv.x, r1 * sv.y);
                }
            }
        }
        __syncwarp();
        sb ^= 1;
    }
    CP_WAIT0();
}

// ---------------- K5: node update (4 nodes/block, fused reductions) ----------
__global__ void __launch_bounds__(256)
k_node_update(const float* __restrict__ attrs,
              const int*   __restrict__ batch,
              const float* __restrict__ PW,    // prod_w[l]  [10,64]
              const float* __restrict__ CW,    // charge_w[l][64]
              const float* __restrict__ ROW,   // readout_w[l][64] (l==0)
              const float* __restrict__ RW1,   // ro2_w1 [64,16]
              const float* __restrict__ RB1,   // ro2_b1 [16]
              const float* __restrict__ RW2,   // ro2_w2 [16]
              float* __restrict__ out,
              int last, int cidx) {
    int lg = threadIdx.x >> 6;
    int f  = threadIdx.x & 63;
    int n  = blockIdx.x * 4 + lg;
    __shared__ float at[4][NELS];
    __shared__ float scsm[4][FF];
    __shared__ float redc[4][FF];
    __shared__ float rede[4][FF];
    __shared__ float resc[4], rese[4];
    if (f < NELS) at[lg][f] = attrs[n * NELS + f];
    __syncthreads();
    float a = g_agg[n * FF + f] * 0.0625f;   // / AVG_NEIGH
    g_agg[n * FF + f] = 0.0f;                // pre-zero for next layer
    float pw = 0.0f;
#pragma unroll
    for (int k = 0; k < NELS; k++) pw = fmaf(at[lg][k], PW[k * FF + f], pw);
    float sc = fmaf(a, a, a) + g_sc[n * FF + f] * pw;
    g_sc[n * FF + f] = sc;
    scsm[lg][f] = sc;
    redc[lg][f] = sc * CW[f];
    if (!last) rede[lg][f] = sc * ROW[f];
    __syncthreads();
    if (f < 32) {
        float vc = redc[lg][f] + redc[lg][f + 32];
        float ve = last ? 0.0f : (rede[lg][f] + rede[lg][f + 32]);
        vc += __shfl_down_sync(0xffffffffu, vc, 16);
        ve += __shfl_down_sync(0xffffffffu, ve, 16);
        vc += __shfl_down_sync(0xffffffffu, vc, 8);
        ve += __shfl_down_sync(0xffffffffu, ve, 8);
        vc += __shfl_down_sync(0xffffffffu, vc, 4);
        ve += __shfl_down_sync(0xffffffffu, ve, 4);
        vc += __shfl_down_sync(0xffffffffu, vc, 2);
        ve += __shfl_down_sync(0xffffffffu, ve, 2);
        vc += __shfl_down_sync(0xffffffffu, vc, 1);
        ve += __shfl_down_sync(0xffffffffu, ve, 1);
        if (f == 0) { resc[lg] = vc; rese[lg] = ve; }
    }
    if (last) {
        if (f < HML) {
            float acc = RB1[f];
#pragma unroll
            for (int j = 0; j < FF; j++) acc = fmaf(scsm[lg][j], RW1[j * HML + f], acc);
            float hv = __fdividef(acc, 1.0f + __expf(-acc));
            rede[lg][f] = hv * RW2[f];
        }
        __syncthreads();
        if (f == 0) {
            float v = 0.0f;
#pragma unroll
            for (int m = 0; m < HML; m++) v += rede[lg][m];
            rese[lg] = v;
        }
    }
    if (f == 0) {
        g_cd[n] += resc[lg];
        out[OUT_NE + n] += rese[lg];
        atomicAdd(&out[OUT_CONTRIB + batch[n] * 3 + cidx], rese[lg]);
    }
}

// ---------------- K6: screened Coulomb + total charge + finalize -------------
// 32 blocks/graph: 32 i-rows x 8 j-chunks, 125 inner iters per thread.
__global__ void __launch_bounds__(256)
k_coulomb(float* __restrict__ out) {
    int g = blockIdx.x >> 5;          // 32 blocks per graph
    int ipart = blockIdx.x & 31;
    __shared__ float4 pq[NGG];        // (x, y, z, q) — one LDS.128 per pair
    int base = g * NGG;
    float qpart = 0.0f;
    for (int j = threadIdx.x; j < NGG; j += 256) {
        float q = g_cd[base + j];
        qpart += q;
        float4 p4 = g_pos4[base + j];
        pq[j] = make_float4(p4.x, p4.y, p4.z, q);
    }
    __syncthreads();
    int il = ipart * 32 + (threadIdx.x & 31);
    int jc = threadIdx.x >> 5;        // 0..7
    float e = 0.0f;
    if (il < NGG) {
        float4 me = pq[il];
        float xi = me.x, yi = me.y, zi = me.z, qi = me.w;
        float acc = 0.0f;
        for (int j = jc; j < NGG; j += 8) {
            float4 v = pq[j];
            float dx = xi - v.x, dy = yi - v.y, dz = zi - v.z;
            float d2 = fmaf(dx, dx, fmaf(dy, dy, dz * dz)) + 1e-12f;
            float rinv = rsqrtf(d2);
            float r = d2 * rinv;
            acc = fmaf(v.w, erff(0.5f * r) * rinv, acc);
        }
        if ((il & 7) == jc) {
            float rinv = rsqrtf(1e-12f);
            float r = 1e-12f * rinv;
            acc -= qi * erff(0.5f * r) * rinv;     // subtract self term
        }
        e = 0.5f * qi * acc;
    }
    // block reduce e (and qpart)
    __shared__ float wred[8], wq[8];
    float v = e, q = qpart;
    v += __shfl_down_sync(0xffffffffu, v, 16);
    q += __shfl_down_sync(0xffffffffu, q, 16);
    v += __shfl_down_sync(0xffffffffu, v, 8);
    q += __shfl_down_sync(0xffffffffu, q, 8);
    v += __shfl_down_sync(0xffffffffu, v, 4);
    q += __shfl_down_sync(0xffffffffu, q, 4);
    v += __shfl_down_sync(0xffffffffu, v, 2);
    q += __shfl_down_sync(0xffffffffu, q, 2);
    v += __shfl_down_sync(0xffffffffu, v, 1);
    q += __shfl_down_sync(0xffffffffu, q, 1);
    if ((threadIdx.x & 31) == 0) { wred[threadIdx.x >> 5] = v; wq[threadIdx.x >> 5] = q; }
    __syncthreads();
    if (threadIdx.x == 0) {
        float s = 0.0f, qsum = 0.0f;
#pragma unroll
        for (int w = 0; w < 8; w++) { s += wred[w]; qsum += wq[w]; }
        if (ipart == 0) {
            out[OUT_TC + g] = qsum;
            s += out[OUT_CONTRIB + g * 3 + 0]
               + out[OUT_CONTRIB + g * 3 + 1]
               + out[OUT_CONTRIB + g * 3 + 2];
        }
        atomicAdd(&out[OUT_TE + g], s);
    }
}

// ---------------- launch ----------------
extern "C" void kernel_launch(void* const* d_in, const int* in_sizes, int n_in,
                              void* d_out, int out_size) {
    const float* node_attrs = (const float*)d_in[0];   // [N,10]
    const float* positions  = (const float*)d_in[1];   // [N,3]
    const int*   edge_index = (const int*)d_in[2];     // [2,E]
    const int*   batch      = (const int*)d_in[3];     // [N]
    int p = (in_sizes[4] == NELS) ? 4 : 5;
    const float* atomic_energies = (const float*)d_in[p + 0];   // [10]
    const float* embed_w         = (const float*)d_in[p + 1];   // [10,64]
    const float* radial_w1       = (const float*)d_in[p + 2];   // [2,8,64]
    const float* radial_b1       = (const float*)d_in[p + 3];   // [2,64]
    const float* radial_w2       = (const float*)d_in[p + 4];   // [2,64,64]
    const float* prod_w          = (const float*)d_in[p + 5];   // [2,10,64]
    const float* readout_w       = (const float*)d_in[p + 6];   // [2,64]
    const float* ro2_w1          = (const float*)d_in[p + 7];   // [64,16]
    const float* ro2_b1          = (const float*)d_in[p + 8];   // [16]
    const float* ro2_w2          = (const float*)d_in[p + 9];   // [16]
    const float* charge_w        = (const float*)d_in[p + 10];  // [2,64]
    const float* flux_w          = (const float*)d_in[p + 11];  // [2,8]
    const float* formal_charges  = (const float*)d_in[p + 12];  // [10]
    float* out = (float*)d_out;

    k_zero<<<1, 256>>>(out);
    k_node_init<<<NN / 4, 256>>>(node_attrs, positions, batch,
                                 atomic_energies, embed_w, formal_charges, out);
    k_edge_geom<<<EE / 256, 256>>>(edge_index, batch, flux_w, out);

    for (int l = 0; l < 2; l++) {
        k_edge_mlp<<<444, 256>>>(radial_w1 + l * NBB * FF,
                                 radial_b1 + l * FF,
                                 radial_w2 + l * FF * FF);
        k_node_update<<<NN / 4, 256>>>(node_attrs, batch,
                                       prod_w + l * NELS * FF,
                                       charge_w + l * FF,
                                       readout_w + l * FF,
                                       ro2_w1, ro2_b1, ro2_w2,
                                       out, (l == 1) ? 1 : 0, l + 1);
    }

    k_coulomb<<<GG * 32, 256>>>(out);
}

// round 10
// speedup vs baseline: 1.1273x; 1.0425x over previous
#include <cuda_runtime.h>
#include <math.h>

#define NN   20000
#define FF   64
#define EE   320000
#define GG   20
#define NGG  1000
#define NELS 10
#define NBB  8
#define RMAXF 5.0f
#define HML  16

// output layout (float32, 20160 elems):
#define OUT_TE      0        // [20]  total_energy
#define OUT_NE      20       // [20000] node_energy
#define OUT_CONTRIB 20020    // [20,3] contributions
#define OUT_POL     20080    // [20,3] pol
#define OUT_TC      20140    // [20]  total_charge
#define OUT_TOTAL   20160

// ---------------- device scratch (no allocation allowed) ----------------
__device__ float  g_sc[NN * FF];     // current node scalars
__device__ float  g_agg[NN * FF];    // per-layer aggregation (s=0 only!)
__device__ float  g_ef[EE * NBB];    // compacted active-edge radial features
__device__ int2   g_aidx[EE];        // compacted (snd, rcv)
__device__ float  g_cd[NN];          // charge density
__device__ float4 g_pos4[NN];        // padded positions (1-sector gathers)
__device__ int    g_count;           // active edge count

// ---------------- PTX helpers ----------------
__device__ __forceinline__ unsigned smem_u32(const void* p) {
    return (unsigned)__cvta_generic_to_shared(p);
}
__device__ __forceinline__ void cp16(unsigned d, const void* g) {
    asm volatile("cp.async.ca.shared.global [%0], [%1], 16;" :: "r"(d), "l"(g));
}
__device__ __forceinline__ void cp8(unsigned d, const void* g) {
    asm volatile("cp.async.ca.shared.global [%0], [%1], 8;" :: "r"(d), "l"(g));
}
#define CP_COMMIT()  asm volatile("cp.async.commit_group;" ::: "memory")
#define CP_WAIT0()   asm volatile("cp.async.wait_group 0;" ::: "memory")

__device__ __forceinline__ unsigned long long pack2(float x, float y) {
    unsigned long long r;
    asm("mov.b64 %0, {%1, %2};" : "=l"(r) : "f"(x), "f"(y));
    return r;
}
__device__ __forceinline__ void ffma2(unsigned long long& d,
                                      unsigned long long a, unsigned long long b) {
    asm("fma.rn.f32x2 %0, %1, %2, %3;" : "=l"(d) : "l"(a), "l"(b), "l"(d));
}
__device__ __forceinline__ float2 unpack2(unsigned long long v) {
    float2 r;
    asm("mov.b64 {%0, %1}, %2;" : "=f"(r.x), "=f"(r.y) : "l"(v));
    return r;
}
// vector reduction: one REDG.64 for two adjacent floats (sm_90+)
__device__ __forceinline__ void red_v2(float* p, float a, float b) {
    asm volatile("red.global.add.v2.f32 [%0], {%1, %2};"
                 :: "l"(p), "f"(a), "f"(b) : "memory");
}
// branchless erf for x >= 0 (A&S 7.1.26, |err| <= 1.5e-7)
__device__ __forceinline__ float erf_fast(float x) {
    float t = __fdividef(1.0f, fmaf(0.3275911f, x, 1.0f));
    float p = t * fmaf(t, fmaf(t, fmaf(t, fmaf(t, 1.061405429f, -1.453152027f),
                                       1.421413741f), -0.284496736f), 0.254829592f);
    return 1.0f - p * __expf(-x * x);
}

// ---------------- K0: zero small accumulator regions ----------------
__global__ void k_zero(float* __restrict__ out) {
    int i = threadIdx.x;
    if (i < GG) out[OUT_TE + i] = 0.0f;                         // total_energy
    if (i < 140) out[OUT_CONTRIB + i] = 0.0f;                   // contrib+pol+tc
    if (i == 0) g_count = 0;
}

// ---------------- K1: node init (embed, E0, FQ, pol, pos4; 4 nodes/block) ---
__global__ void __launch_bounds__(256)
k_node_init(const float* __restrict__ attrs,
            const float* __restrict__ pos,
            const int*   __restrict__ batch,
            const float* __restrict__ ae,
            const float* __restrict__ embw,
            const float* __restrict__ fc,
            float* __restrict__ out) {
    int lg = threadIdx.x >> 6;
    int f  = threadIdx.x & 63;
    int n  = blockIdx.x * 4 + lg;
    __shared__ float at[4][NELS];
    __shared__ float fqs[4];
    if (f < NELS) at[lg][f] = attrs[n * NELS + f];
    __syncthreads();
    float s = 0.0f;
#pragma unroll
    for (int k = 0; k < NELS; k++) s = fmaf(at[lg][k], embw[k * FF + f], s);
    g_sc[n * FF + f] = s;
    g_agg[n * FF + f] = 0.0f;
    if (f == 0) {
        float fq = 0.0f, ne0 = 0.0f;
#pragma unroll
        for (int k = 0; k < NELS; k++) { fq = fmaf(at[lg][k], fc[k], fq); ne0 = fmaf(at[lg][k], ae[k], ne0); }
        g_cd[n] = fq;
        out[OUT_NE + n] = ne0;
        atomicAdd(&out[OUT_CONTRIB + batch[n] * 3 + 0], ne0);
        fqs[lg] = fq;
        g_pos4[n] = make_float4(pos[n * 3 + 0], pos[n * 3 + 1], pos[n * 3 + 2], 0.0f);
    }
    __syncthreads();
    if (f < 3)
        atomicAdd(&out[OUT_POL + batch[n] * 3 + f], fqs[lg] * pos[n * 3 + f]);
}

// ---------------- K2: edge geometry + radial basis + flux/pol + compaction ---
__global__ void __launch_bounds__(256)
k_edge_geom(const int*   __restrict__ ei,
            const int*   __restrict__ batch,
            const float* __restrict__ fw,   // flux_w [2,8]
            float* __restrict__ out) {
    int e = blockIdx.x * 256 + threadIdx.x;    // grid sized exactly EE/256
    int lane = threadIdx.x & 31;
    __shared__ float polsm[GG * 3];
    if (threadIdx.x < GG * 3) polsm[threadIdx.x] = 0.0f;
    __syncthreads();

    int snd = ei[e], rcv = ei[EE + e];
    float4 ps = g_pos4[snd], pr = g_pos4[rcv];
    float dx = pr.x - ps.x, dy = pr.y - ps.y, dz = pr.z - ps.z;
    float d2 = fmaf(dx, dx, fmaf(dy, dy, dz * dz)) + 1e-12f;
    float rinv = rsqrtf(d2);
    float r = d2 * rinv;
    bool active = (r < RMAXF);
    float ef[NBB];
    float flux = 0.0f;
    if (active) {
        float x = r * (1.0f / RMAXF);
        float x2 = x * x;
        float x5 = x2 * x2 * x;
        float u = 1.0f + x5 * (-21.0f + x * (35.0f - 15.0f * x));
        float pref = 0.6324555320336759f * u * rinv;    // sqrt(2/5)*u/r
        float s1, c1;
        __sincosf(r * 0.6283185307179586f, &s1, &c1);   // pi/5 * r
        float sn = s1, cn = c1;
#pragma unroll
        for (int i = 0; i < NBB; i++) {
            float v = pref * sn;
            ef[i] = v;
            flux = fmaf(v, fw[i] + fw[NBB + i], flux);
            float sn2 = sn * c1 + cn * s1;
            cn = cn * c1 - sn * s1;
            sn = sn2;
        }
    }

    unsigned mask = __ballot_sync(0xffffffffu, active);
    if (mask) {
        int leader = __ffs(mask) - 1;
        int cnt = __popc(mask);
        int base = 0;
        if (lane == leader) base = atomicAdd(&g_count, cnt);
        base = __shfl_sync(0xffffffffu, base, leader);
        if (active) {
            int slot = base + __popc(mask & ((1u << lane) - 1u));
            float4* ef4 = (float4*)&g_ef[slot * NBB];
            ef4[0] = make_float4(ef[0], ef[1], ef[2], ef[3]);
            ef4[1] = make_float4(ef[4], ef[5], ef[6], ef[7]);
            g_aidx[slot] = make_int2(snd, rcv);
            int g = batch[rcv];
            atomicAdd(&polsm[g * 3 + 0], flux * dx);
            atomicAdd(&polsm[g * 3 + 1], flux * dy);
            atomicAdd(&polsm[g * 3 + 2], flux * dz);
        }
    }
    __syncthreads();
    if (threadIdx.x < GG * 3) {
        float v = polsm[threadIdx.x];
        if (v != 0.0f) atomicAdd(&out[OUT_POL + threadIdx.x], v);
    }
}

// ---------------- K4: per-edge radial MLP + message scatter (s=0 only) -------
// R9 design, but 4 blocks/SM (forced <=64 regs; spills are L1-local and cold)
// to raise occupancy 34.6% -> ~50% in this latency-bound kernel.
__global__ void __launch_bounds__(256, 4)
k_edge_mlp(const float* __restrict__ W1,   // [8,64]
           const float* __restrict__ B1,   // [64]
           const float* __restrict__ W2) { // [64,64]
    __shared__ float4 w2t4[FF][17];        // physical rows: pi-permuted f
    __shared__ float2 hp[8][4][FF];        // [warp][edge-pair][pi(j)]
    __shared__ float4 efb[2][8][8][2];     // [stage][warp][edge][2xfloat4]
    __shared__ int2   idb[2][8][8];        // [stage][warp][edge]
    int tid = threadIdx.x;
    int warp = tid >> 5;
    int lane = tid & 31;
    int f0 = 2 * lane, f1 = 2 * lane + 1;  // logical features of this lane

    {   // cooperative transpose of W2 into smem with pi-permuted row index:
        // physical row pi(f) = (f>>1) + (f&1)*32  ==> lane reads rows l, l+32
        int fl = tid & 63;
        int prow = (fl >> 1) + (fl & 1) * 32;
        int q  = tid >> 6;
        float* w2s = (float*)w2t4;         // row stride 68 floats
        for (int j = q; j < FF; j += 4) {
            int jp = (j >> 1) + (j & 1) * 32;     // pi on the j index too
            w2s[prow * 68 + jp] = W2[j * FF + fl];
        }
    }
    float w1a[NBB], w1b[NBB];
#pragma unroll
    for (int i = 0; i < NBB; i++) { w1a[i] = W1[i * FF + f0]; w1b[i] = W1[i * FF + f1]; }
    float b1a = B1[f0], b1b = B1[f1];
    __syncthreads();

    int count = g_count;
    int stride = gridDim.x * 64;

    // prologue: prefetch trip 0 into stage 0
    {
        int slot = blockIdx.x * 64 + warp * 8 + lane;
        if (lane < 8 && slot < count) {
            cp16(smem_u32(&efb[0][warp][lane][0]), &g_ef[slot * NBB]);
            cp16(smem_u32(&efb[0][warp][lane][1]), &g_ef[slot * NBB + 4]);
            cp8(smem_u32(&idb[0][warp][lane]), &g_aidx[slot]);
        }
        CP_COMMIT();
    }

    int sb = 0;
    for (int tb = blockIdx.x * 64; tb < count; tb += stride) {
        int base = tb + warp * 8;
        CP_WAIT0();
        __syncwarp();
        // prefetch next trip into the other stage
        {
            int slot = tb + stride + warp * 8 + lane;
            if (lane < 8 && slot < count) {
                cp16(smem_u32(&efb[sb ^ 1][warp][lane][0]), &g_ef[slot * NBB]);
                cp16(smem_u32(&efb[sb ^ 1][warp][lane][1]), &g_ef[slot * NBB + 4]);
                cp8(smem_u32(&idb[sb ^ 1][warp][lane]), &g_aidx[slot]);
            }
            CP_COMMIT();
        }
        // phase 1: hidden units f0, f1 for 8 edges; store at physical rows
        // pi(f0)=lane, pi(f1)=lane+32.
#pragma unroll
        for (int e = 0; e < 8; e++) {
            int slot = base + e;
            float h0 = 0.0f, h1 = 0.0f;
            if (slot < count) {
                float4 a = efb[sb][warp][e][0];
                float4 b = efb[sb][warp][e][1];
                float acc0 = b1a, acc1 = b1b;
                acc0 = fmaf(a.x, w1a[0], acc0); acc1 = fmaf(a.x, w1b[0], acc1);
                acc0 = fmaf(a.y, w1a[1], acc0); acc1 = fmaf(a.y, w1b[1], acc1);
                acc0 = fmaf(a.z, w1a[2], acc0); acc1 = fmaf(a.z, w1b[2], acc1);
                acc0 = fmaf(a.w, w1a[3], acc0); acc1 = fmaf(a.w, w1b[3], acc1);
                acc0 = fmaf(b.x, w1a[4], acc0); acc1 = fmaf(b.x, w1b[4], acc1);
                acc0 = fmaf(b.y, w1a[5], acc0); acc1 = fmaf(b.y, w1b[5], acc1);
                acc0 = fmaf(b.z, w1a[6], acc0); acc1 = fmaf(b.z, w1b[6], acc1);
                acc0 = fmaf(b.w, w1a[7], acc0); acc1 = fmaf(b.w, w1b[7], acc1);
                h0 = __fdividef(acc0, 1.0f + __expf(-acc0));     // silu (MUFU)
                h1 = __fdividef(acc1, 1.0f + __expf(-acc1));
            }
            ((float*)&hp[warp][e >> 1][lane])[e & 1] = h0;        // pi(f0)
            ((float*)&hp[warp][e >> 1][lane + 32])[e & 1] = h1;   // pi(f1)
        }
        __syncwarp();
        // phase 2: packed f32x2 GEMM over permuted hidden index (invariant).
        unsigned long long A0[4], A1[4];
#pragma unroll
        for (int ep = 0; ep < 4; ep++) { A0[ep] = 0ull; A1[ep] = 0ull; }
#pragma unroll
        for (int j4 = 0; j4 < 16; j4++) {
            float4 wl4 = w2t4[lane][j4];           // feature f0 (phys row lane)
            float4 wh4 = w2t4[lane + 32][j4];      // feature f1
            unsigned long long pwl0 = pack2(wl4.x, wl4.x);
            unsigned long long pwl1 = pack2(wl4.y, wl4.y);
            unsigned long long pwl2 = pack2(wl4.z, wl4.z);
            unsigned long long pwl3 = pack2(wl4.w, wl4.w);
            unsigned long long pwh0 = pack2(wh4.x, wh4.x);
            unsigned long long pwh1 = pack2(wh4.y, wh4.y);
            unsigned long long pwh2 = pack2(wh4.z, wh4.z);
            unsigned long long pwh3 = pack2(wh4.w, wh4.w);
#pragma unroll
            for (int ep = 0; ep < 4; ep++) {
                ulonglong2 hA = *(const ulonglong2*)&hp[warp][ep][j4 * 4];
                ulonglong2 hB = *(const ulonglong2*)&hp[warp][ep][j4 * 4 + 2];
                ffma2(A0[ep], hA.x, pwl0); ffma2(A1[ep], hA.x, pwh0);
                ffma2(A0[ep], hA.y, pwl1); ffma2(A1[ep], hA.y, pwh1);
                ffma2(A0[ep], hB.x, pwl2); ffma2(A1[ep], hB.x, pwh2);
                ffma2(A0[ep], hB.y, pwl3); ffma2(A1[ep], hB.y, pwh3);
            }
        }
        // phase 3: LDG.64 sc gather + red.v2 scatter (adjacent features)
#pragma unroll
        for (int ep = 0; ep < 4; ep++) {
            float2 R0 = unpack2(A0[ep]);   // feature f0 for edges 2ep, 2ep+1
            float2 R1 = unpack2(A1[ep]);   // feature f1
#pragma unroll
            for (int h = 0; h < 2; h++) {
                int slot = base + ep * 2 + h;
                if (slot < count) {
                    int2 sr = idb[sb][warp][ep * 2 + h];
                    float2 sv = __ldg((const float2*)&g_sc[sr.x * FF + f0]);
                    float r0 = h ? R0.y : R0.x;
                    float r1 = h ? R1.y : R1.x;
                    red_v2(&g_agg[sr.y * FF + f0], r0 * sv.x, r1 * sv.y);
                }
            }
        }
        __syncwarp();
        sb ^= 1;
    }
    CP_WAIT0();
}

// ---------------- K5: node update (4 nodes/block, fused reductions) ----------
__global__ void __launch_bounds__(256)
k_node_update(const float* __restrict__ attrs,
              const int*   __restrict__ batch,
              const float* __restrict__ PW,    // prod_w[l]  [10,64]
              const float* __restrict__ CW,    // charge_w[l][64]
              const float* __restrict__ ROW,   // readout_w[l][64] (l==0)
              const float* __restrict__ RW1,   // ro2_w1 [64,16]
              const float* __restrict__ RB1,   // ro2_b1 [16]
              const float* __restrict__ RW2,   // ro2_w2 [16]
              float* __restrict__ out,
              int last, int cidx) {
    int lg = threadIdx.x >> 6;
    int f  = threadIdx.x & 63;
    int n  = blockIdx.x * 4 + lg;
    __shared__ float at[4][NELS];
    __shared__ float scsm[4][FF];
    __shared__ float redc[4][FF];
    __shared__ float rede[4][FF];
    __shared__ float resc[4], rese[4];
    if (f < NELS) at[lg][f] = attrs[n * NELS + f];
    __syncthreads();
    float a = g_agg[n * FF + f] * 0.0625f;   // / AVG_NEIGH
    g_agg[n * FF + f] = 0.0f;                // pre-zero for next layer
    float pw = 0.0f;
#pragma unroll
    for (int k = 0; k < NELS; k++) pw = fmaf(at[lg][k], PW[k * FF + f], pw);
    float sc = fmaf(a, a, a) + g_sc[n * FF + f] * pw;
    g_sc[n * FF + f] = sc;
    scsm[lg][f] = sc;
    redc[lg][f] = sc * CW[f];
    if (!last) rede[lg][f] = sc * ROW[f];
    __syncthreads();
    if (f < 32) {
        float vc = redc[lg][f] + redc[lg][f + 32];
        float ve = last ? 0.0f : (rede[lg][f] + rede[lg][f + 32]);
        vc += __shfl_down_sync(0xffffffffu, vc, 16);
        ve += __shfl_down_sync(0xffffffffu, ve, 16);
        vc += __shfl_down_sync(0xffffffffu, vc, 8);
        ve += __shfl_down_sync(0xffffffffu, ve, 8);
        vc += __shfl_down_sync(0xffffffffu, vc, 4);
        ve += __shfl_down_sync(0xffffffffu, ve, 4);
        vc += __shfl_down_sync(0xffffffffu, vc, 2);
        ve += __shfl_down_sync(0xffffffffu, ve, 2);
        vc += __shfl_down_sync(0xffffffffu, vc, 1);
        ve += __shfl_down_sync(0xffffffffu, ve, 1);
        if (f == 0) { resc[lg] = vc; rese[lg] = ve; }
    }
    if (last) {
        if (f < HML) {
            float acc = RB1[f];
#pragma unroll
            for (int j = 0; j < FF; j++) acc = fmaf(scsm[lg][j], RW1[j * HML + f], acc);
            float hv = __fdividef(acc, 1.0f + __expf(-acc));
            rede[lg][f] = hv * RW2[f];
        }
        __syncthreads();
        if (f == 0) {
            float v = 0.0f;
#pragma unroll
            for (int m = 0; m < HML; m++) v += rede[lg][m];
            rese[lg] = v;
        }
    }
    if (f == 0) {
        g_cd[n] += resc[lg];
        out[OUT_NE + n] += rese[lg];
        atomicAdd(&out[OUT_CONTRIB + batch[n] * 3 + cidx], rese[lg]);
    }
}

// ---------------- K6: screened Coulomb + total charge + finalize -------------
// 32 blocks/graph; branchless erf_fast (A&S 7.1.26) instead of libdevice erff.
__global__ void __launch_bounds__(256)
k_coulomb(float* __restrict__ out) {
    int g = blockIdx.x >> 5;          // 32 blocks per graph
    int ipart = blockIdx.x & 31;
    __shared__ float4 pq[NGG];        // (x, y, z, q) — one LDS.128 per pair
    int base = g * NGG;
    float qpart = 0.0f;
    for (int j = threadIdx.x; j < NGG; j += 256) {
        float q = g_cd[base + j];
        qpart += q;
        float4 p4 = g_pos4[base + j];
        pq[j] = make_float4(p4.x, p4.y, p4.z, q);
    }
    __syncthreads();
    int il = ipart * 32 + (threadIdx.x & 31);
    int jc = threadIdx.x >> 5;        // 0..7
    float e = 0.0f;
    if (il < NGG) {
        float4 me = pq[il];
        float xi = me.x, yi = me.y, zi = me.z, qi = me.w;
        float acc = 0.0f;
        for (int j = jc; j < NGG; j += 8) {
            float4 v = pq[j];
            float dx = xi - v.x, dy = yi - v.y, dz = zi - v.z;
            float d2 = fmaf(dx, dx, fmaf(dy, dy, dz * dz)) + 1e-12f;
            float rinv = rsqrtf(d2);
            float r = d2 * rinv;
            acc = fmaf(v.w, erf_fast(0.5f * r) * rinv, acc);
        }
        if ((il & 7) == jc) {
            float rinv = rsqrtf(1e-12f);
            float r = 1e-12f * rinv;
            acc -= qi * erf_fast(0.5f * r) * rinv;   // subtract self term
        }
        e = 0.5f * qi * acc;
    }
    // block reduce e (and qpart)
    __shared__ float wred[8], wq[8];
    float v = e, q = qpart;
    v += __shfl_down_sync(0xffffffffu, v, 16);
    q += __shfl_down_sync(0xffffffffu, q, 16);
    v += __shfl_down_sync(0xffffffffu, v, 8);
    q += __shfl_down_sync(0xffffffffu, q, 8);
    v += __shfl_down_sync(0xffffffffu, v, 4);
    q += __shfl_down_sync(0xffffffffu, q, 4);
    v += __shfl_down_sync(0xffffffffu, v, 2);
    q += __shfl_down_sync(0xffffffffu, q, 2);
    v += __shfl_down_sync(0xffffffffu, v, 1);
    q += __shfl_down_sync(0xffffffffu, q, 1);
    if ((threadIdx.x & 31) == 0) { wred[threadIdx.x >> 5] = v; wq[threadIdx.x >> 5] = q; }
    __syncthreads();
    if (threadIdx.x == 0) {
        float s = 0.0f, qsum = 0.0f;
#pragma unroll
        for (int w = 0; w < 8; w++) { s += wred[w]; qsum += wq[w]; }
        if (ipart == 0) {
            out[OUT_TC + g] = qsum;
            s += out[OUT_CONTRIB + g * 3 + 0]
               + out[OUT_CONTRIB + g * 3 + 1]
               + out[OUT_CONTRIB + g * 3 + 2];
        }
        atomicAdd(&out[OUT_TE + g], s);
    }
}

// ---------------- launch ----------------
extern "C" void kernel_launch(void* const* d_in, const int* in_sizes, int n_in,
                              void* d_out, int out_size) {
    const float* node_attrs = (const float*)d_in[0];   // [N,10]
    const float* positions  = (const float*)d_in[1];   // [N,3]
    const int*   edge_index = (const int*)d_in[2];     // [2,E]
    const int*   batch      = (const int*)d_in[3];     // [N]
    int p = (in_sizes[4] == NELS) ? 4 : 5;
    const float* atomic_energies = (const float*)d_in[p + 0];   // [10]
    const float* embed_w         = (const float*)d_in[p + 1];   // [10,64]
    const float* radial_w1       = (const float*)d_in[p + 2];   // [2,8,64]
    const float* radial_b1       = (const float*)d_in[p + 3];   // [2,64]
    const float* radial_w2       = (const float*)d_in[p + 4];   // [2,64,64]
    const float* prod_w          = (const float*)d_in[p + 5];   // [2,10,64]
    const float* readout_w       = (const float*)d_in[p + 6];   // [2,64]
    const float* ro2_w1          = (const float*)d_in[p + 7];   // [64,16]
    const float* ro2_b1          = (const float*)d_in[p + 8];   // [16]
    const float* ro2_w2          = (const float*)d_in[p + 9];   // [16]
    const float* charge_w        = (const float*)d_in[p + 10];  // [2,64]
    const float* flux_w          = (const float*)d_in[p + 11];  // [2,8]
    const float* formal_charges  = (const float*)d_in[p + 12];  // [10]
    float* out = (float*)d_out;

    k_zero<<<1, 256>>>(out);
    k_node_init<<<NN / 4, 256>>>(node_attrs, positions, batch,
                                 atomic_energies, embed_w, formal_charges, out);
    k_edge_geom<<<EE / 256, 256>>>(edge_index, batch, flux_w, out);

    for (int l = 0; l < 2; l++) {
        k_edge_mlp<<<592, 256>>>(radial_w1 + l * NBB * FF,
                                 radial_b1 + l * FF,
                                 radial_w2 + l * FF * FF);
        k_node_update<<<NN / 4, 256>>>(node_attrs, batch,
                                       prod_w + l * NELS * FF,
                                       charge_w + l * FF,
                                       readout_w + l * FF,
                                       ro2_w1, ro2_b1, ro2_w2,
                                       out, (l == 1) ? 1 : 0, l + 1);
    }

    k_coulomb<<<GG * 32, 256>>>(out);
}